// round 8
// baseline (speedup 1.0000x reference)
#include <cuda_runtime.h>

#define B_ 128
#define L_ 4096
#define H_ 64
#define V_ 64
#define HALF_ 32
#define C1 0.05f
#define LN_EPS 1e-5f
#define L_PAD (L_ + 8)

typedef unsigned long long ull;

// Token-indexed tables (V=64 tokens): g_hs/g_he are pre-scaled by (1-ALPHA)=C1.
__device__ float g_hs[V_ * HALF_];
__device__ float g_he[V_ * HALF_];
__device__ float g_ks[V_ * HALF_];
__device__ float g_ke[V_ * HALF_];

// ---------------- packed f32x2 helpers ----------------
__device__ __forceinline__ ull fma2(ull a, ull b, ull c) {
    ull d; asm("fma.rn.f32x2 %0,%1,%2,%3;" : "=l"(d) : "l"(a), "l"(b), "l"(c)); return d;
}
__device__ __forceinline__ ull mul2(ull a, ull b) {
    ull d; asm("mul.rn.f32x2 %0,%1,%2;" : "=l"(d) : "l"(a), "l"(b)); return d;
}
__device__ __forceinline__ ull add2(ull a, ull b) {
    ull d; asm("add.rn.f32x2 %0,%1,%2;" : "=l"(d) : "l"(a), "l"(b)); return d;
}
__device__ __forceinline__ ull pack2(float x) {
    ull d; asm("mov.b64 %0,{%1,%1};" : "=l"(d) : "f"(x)); return d;
}
__device__ __forceinline__ float2 unpack2(ull v) {
    float2 r; asm("mov.b64 {%0,%1},%2;" : "=f"(r.x), "=f"(r.y) : "l"(v)); return r;
}
__device__ __forceinline__ float reduce2(ull a0, ull a1) {
    ull s = add2(a0, a1);
    float2 f = unpack2(s);
    float h = f.x + f.y;
    return h + __shfl_xor_sync(0xffffffffu, h, 1);
}

// ---------------------------------------------------------------------------
// Kernel 1: per-token precompute. grid=64 (token), block=128.
// ---------------------------------------------------------------------------
__global__ void build_tables(const float* __restrict__ embed,
                             const float* __restrict__ W1, const float* __restrict__ b1,
                             const float* __restrict__ W2, const float* __restrict__ b2,
                             const float* __restrict__ gamma, const float* __restrict__ beta,
                             const float* __restrict__ Ws, const float* __restrict__ bs,
                             const float* __restrict__ We, const float* __restrict__ be)
{
    __shared__ float s_e[H_];
    __shared__ float s_a[2 * H_];
    __shared__ float s_x[H_];
    __shared__ float s_h[H_];
    __shared__ float s_mu, s_rstd;

    int tok = blockIdx.x;
    int tid = threadIdx.x;

    if (tid < H_) s_e[tid] = embed[tok * H_ + tid];
    __syncthreads();

    {
        float acc = b1[tid];
        #pragma unroll 32
        for (int h = 0; h < H_; ++h) acc = fmaf(s_e[h], __ldg(W1 + h * 2 * H_ + tid), acc);
        s_a[tid] = fmaxf(acc, 0.0f);
    }
    __syncthreads();

    if (tid < H_) {
        float acc = b2[tid];
        #pragma unroll 32
        for (int k = 0; k < 2 * H_; ++k) acc = fmaf(s_a[k], __ldg(W2 + k * H_ + tid), acc);
        s_x[tid] = s_e[tid] + acc;
    }
    __syncthreads();

    if (tid == 0) {
        float mu = 0.f;
        for (int i = 0; i < H_; ++i) mu += s_x[i];
        mu *= (1.0f / H_);
        float var = 0.f;
        for (int i = 0; i < H_; ++i) { float d = s_x[i] - mu; var = fmaf(d, d, var); }
        var *= (1.0f / H_);
        s_mu = mu;
        s_rstd = rsqrtf(var + LN_EPS);
    }
    __syncthreads();

    if (tid < H_) s_h[tid] = (s_x[tid] - s_mu) * s_rstd * gamma[tid] + beta[tid];
    __syncthreads();

    int wid = tid >> 5, lane = tid & 31;
    if (wid == 0) {
        float acc = bs[lane];
        #pragma unroll 32
        for (int j = 0; j < H_; ++j) acc = fmaf(s_h[j], __ldg(Ws + j * HALF_ + lane), acc);
        float ss = acc * acc;
        #pragma unroll
        for (int m = 16; m > 0; m >>= 1) ss += __shfl_xor_sync(0xffffffffu, ss, m);
        float n = fmaxf(sqrtf(ss), 1e-12f);
        g_hs[tok * HALF_ + lane] = C1 * acc;
        g_ks[tok * HALF_ + lane] = acc / n;
    } else if (wid == 1) {
        float acc = be[lane];
        #pragma unroll 32
        for (int j = 0; j < H_; ++j) acc = fmaf(s_h[j], __ldg(We + j * HALF_ + lane), acc);
        float ss = acc * acc;
        #pragma unroll
        for (int m = 16; m > 0; m >>= 1) ss += __shfl_xor_sync(0xffffffffu, ss, m);
        float n = fmaxf(sqrtf(ss), 1e-12f);
        g_he[tok * HALF_ + lane] = C1 * acc;
        g_ke[tok * HALF_ + lane] = acc / n;
    }
}

// ---------------------------------------------------------------------------
// Kernel 2: delta-rule scan, RANK-2 steps (token pair per iteration).
// grid = B (one batch per CTA/SM), block = 128 (4 warps -> 4 SMSPs).
// Warps 0,1: M_s; warps 2,3: M_e. Lane owns half a row (16 cols = 8 f32x2).
// Per iter (pair t,t+1):
//   - dots for pair (t+2,t+3) issued on PRE-update m = M^(t); reduced same
//     iter (shfl crosses iter boundary as loop-carried red0/red1)
//   - consumed next iter with 5 Gram corrections (d_{t-2}, d_{t-1}, d_t terms)
//   - serial chain: 4 FFMAs (d_{t-1} -> ps_t -> d_t -> ps_{t+1} -> d_{t+1})
// ---------------------------------------------------------------------------
__global__ __launch_bounds__(128, 1)
void scan_kernel(const int* __restrict__ seq,
                 const float* __restrict__ Wrp, const float* __restrict__ brp,
                 const float* __restrict__ Wout, const float* __restrict__ bout,
                 float* __restrict__ out)
{
    extern __shared__ float sm[];
    float* s_ks = sm;                          // 2048
    float* s_ke = sm + 2048;                   // 2048
    float* s_hs = sm + 4096;                   // 2048
    float* s_he = sm + 6144;                   // 2048
    float* s_Gs = sm + 8192;                   // 4096
    float* s_Ge = sm + 12288;                  // 4096
    int*   s_seq = (int*)(sm + 16384);         // L_+8 ints
    float* s_r   = sm + 16384 + L_PAD;         // 64
    float* s_tmp = s_r + 64;                   // 64

    const int b = blockIdx.x;
    const int tid = threadIdx.x;
    const int w = tid >> 5;
    const int lane = tid & 31;

    // stage sequence + tables
    {
        const int* seqb = seq + b * L_;
        for (int k = tid; k < L_; k += 128) s_seq[k] = seqb[k];
        if (tid < 8) s_seq[L_ + tid] = 0;
    }
    for (int k = tid; k < V_ * HALF_; k += 128) {
        s_ks[k] = g_ks[k];
        s_ke[k] = g_ke[k];
        s_hs[k] = g_hs[k];
        s_he[k] = g_he[k];
    }
    __syncthreads();

    // Gram tables computed in-CTA from staged keys (symmetric)
    for (int idx = tid; idx < V_ * V_; idx += 128) {
        const int a = idx >> 6, c = idx & 63;
        float ss = 0.f, se = 0.f;
        #pragma unroll
        for (int j = 0; j < HALF_; ++j) {
            ss = fmaf(s_ks[a * HALF_ + j], s_ks[c * HALF_ + j], ss);
            se = fmaf(s_ke[a * HALF_ + j], s_ke[c * HALF_ + j], se);
        }
        s_Gs[idx] = ss;
        s_Ge[idx] = se;
    }
    __syncthreads();

    const bool is_e = (w >= 2);
    const int row = ((w & 1) << 4) | (lane >> 1);
    const int col0 = (lane & 1) << 4;
    const float* kT = is_e ? s_ke : s_ks;
    const float* hT = is_e ? s_he : s_hs;
    const float* gT = is_e ? s_Ge : s_Gs;
    const float invL = 1.0f / (float)L_;

    ull m[8], kA0[8], kA1[8], kB0[8], kB1[8], kt[8];

    #define LOADK(DST, TOK) { \
        const ulonglong2* p_ = (const ulonglong2*)(kT + ((TOK) << 5) + col0); \
        ulonglong2 x_ = p_[0], y_ = p_[1]; \
        DST[0] = x_.x; DST[1] = x_.y; DST[2] = y_.x; DST[3] = y_.y; \
        const ulonglong2* q_ = (const ulonglong2*)(kT + ((TOK) << 5) + col0 + 8); \
        ulonglong2 z_ = q_[0], u_ = q_[1]; \
        DST[4] = z_.x; DST[5] = z_.y; DST[6] = u_.x; DST[7] = u_.y; }

    // ================= prologue: steps 0,1,2 =================
    const int v0 = s_seq[0], v1 = s_seq[1], v2 = s_seq[2];
    int vt0 = s_seq[3], vt1 = s_seq[4], vt2 = s_seq[5], vt3 = s_seq[6];

    const float sc_0 = is_e ? invL : 1.0f;
    const float sc_1 = is_e ? 2.0f * invL : 1.0f;
    const float sc_2 = is_e ? 3.0f * invL : 1.0f;

    // step 0 (ps = 0)
    const float d0p = sc_0 * hT[(v0 << 5) + row];
    LOADK(kt, v0);
    {
        const ull d2_ = pack2(d0p);
        #pragma unroll
        for (int j = 0; j < 8; ++j) m[j] = mul2(d2_, kt[j]);     // M^(1)
    }

    // dots of k_3, k_4 on M^(1) (pre-update relative to pair (1,2))
    LOADK(kA0, vt0);
    LOADK(kA1, vt1);
    float red0, red1;
    {
        ull a0 = mul2(m[0], kA0[0]), a1 = mul2(m[1], kA0[1]);
        a0 = fma2(m[2], kA0[2], a0); a1 = fma2(m[3], kA0[3], a1);
        a0 = fma2(m[4], kA0[4], a0); a1 = fma2(m[5], kA0[5], a1);
        a0 = fma2(m[6], kA0[6], a0); a1 = fma2(m[7], kA0[7], a1);
        ull b0 = mul2(m[0], kA1[0]), b1 = mul2(m[1], kA1[1]);
        b0 = fma2(m[2], kA1[2], b0); b1 = fma2(m[3], kA1[3], b1);
        b0 = fma2(m[4], kA1[4], b0); b1 = fma2(m[5], kA1[5], b1);
        b0 = fma2(m[6], kA1[6], b0); b1 = fma2(m[7], kA1[7], b1);
        red0 = reduce2(a0, a1);
        red1 = reduce2(b0, b1);
    }

    // steps 1,2 (exact ps via Gram)
    const float g01 = gT[(v0 << 6) + v1];
    const float g02 = gT[(v0 << 6) + v2];
    const float g12 = gT[(v1 << 6) + v2];
    const float ps1p = d0p * g01;
    const float d1p = fmaf(-C1 * sc_1, ps1p, sc_1 * hT[(v1 << 5) + row]);
    const float ps2p = fmaf(d1p, g12, d0p * g02);
    const float d2p = fmaf(-C1 * sc_2, ps2p, sc_2 * hT[(v2 << 5) + row]);
    LOADK(kt, v1);
    {
        const ull d2_ = pack2(d1p);
        #pragma unroll
        for (int j = 0; j < 8; ++j) m[j] = fma2(d2_, kt[j], m[j]);
    }
    LOADK(kt, v2);
    {
        const ull d2_ = pack2(d2p);
        #pragma unroll
        for (int j = 0; j < 8; ++j) m[j] = fma2(d2_, kt[j], m[j]);   // M^(3)
    }

    float dm2 = d1p, dm1 = d2p;

    // scalars for pair (3,4)
    float g0 = gT[(vt0 << 6) + v1];   // G(v1, v3)
    float g1 = gT[(vt0 << 6) + v2];   // G(v2, v3)
    float g2 = gT[(vt1 << 6) + v1];   // G(v1, v4)
    float g3 = gT[(vt1 << 6) + v2];   // G(v2, v4)
    float g4 = gT[(vt1 << 6) + vt0];  // G(v3, v4)
    float sc0 = is_e ? 4.0f * invL : 1.0f;
    float sc1 = is_e ? 5.0f * invL : 1.0f;
    const float sc2step = is_e ? 2.0f * invL : 0.0f;
    float hsc0 = sc0 * hT[(vt0 << 5) + row], csc0 = -C1 * sc0;
    float hsc1 = sc1 * hT[(vt1 << 5) + row], csc1 = -C1 * sc1;

    // ================= main loop: pairs (t, t+1), t = 3,5,...,4093 ==========
    #define PAIR(T, KU0, KU1, KL0, KL1) { \
        const int va_ = s_seq[(T) + 4]; \
        const int vb_ = s_seq[(T) + 5]; \
        LOADK(KL0, vt2); \
        LOADK(KL1, vt3); \
        /* serial chain (4 FFMAs from dm1) */ \
        const float ps0_ = fmaf(dm1, g1, fmaf(dm2, g0, red0)); \
        const float d0_  = fmaf(csc0, ps0_, hsc0); \
        const float ps1_ = fmaf(d0_, g4, fmaf(dm1, g3, fmaf(dm2, g2, red1))); \
        const float d1_  = fmaf(csc1, ps1_, hsc1); \
        /* dots of k_{T+2},k_{T+3} on PRE-update m = M^(T) */ \
        ull a0_ = mul2(m[0], KL0[0]), a1_ = mul2(m[1], KL0[1]); \
        a0_ = fma2(m[2], KL0[2], a0_); a1_ = fma2(m[3], KL0[3], a1_); \
        a0_ = fma2(m[4], KL0[4], a0_); a1_ = fma2(m[5], KL0[5], a1_); \
        a0_ = fma2(m[6], KL0[6], a0_); a1_ = fma2(m[7], KL0[7], a1_); \
        ull b0_ = mul2(m[0], KL1[0]), b1_ = mul2(m[1], KL1[1]); \
        b0_ = fma2(m[2], KL1[2], b0_); b1_ = fma2(m[3], KL1[3], b1_); \
        b0_ = fma2(m[4], KL1[4], b0_); b1_ = fma2(m[5], KL1[5], b1_); \
        b0_ = fma2(m[6], KL1[6], b0_); b1_ = fma2(m[7], KL1[7], b1_); \
        red0 = reduce2(a0_, a1_); \
        red1 = reduce2(b0_, b1_); \
        /* next-pair Gram / h / scale prefetch (all off-chain) */ \
        const int b2_ = vt2 << 6, b3_ = vt3 << 6; \
        const float g0n_ = gT[b2_ + vt0], g1n_ = gT[b2_ + vt1]; \
        const float g2n_ = gT[b3_ + vt0], g3n_ = gT[b3_ + vt1], g4n_ = gT[b3_ + vt2]; \
        const float h0n_ = hT[(vt2 << 5) + row], h1n_ = hT[(vt3 << 5) + row]; \
        sc0 += sc2step; sc1 += sc2step; \
        /* rank-2 update: m = M^(T+2) */ \
        const ull d02_ = pack2(d0_), d12_ = pack2(d1_); \
        m[0] = fma2(d02_, KU0[0], m[0]); m[1] = fma2(d02_, KU0[1], m[1]); \
        m[2] = fma2(d02_, KU0[2], m[2]); m[3] = fma2(d02_, KU0[3], m[3]); \
        m[4] = fma2(d02_, KU0[4], m[4]); m[5] = fma2(d02_, KU0[5], m[5]); \
        m[6] = fma2(d02_, KU0[6], m[6]); m[7] = fma2(d02_, KU0[7], m[7]); \
        m[0] = fma2(d12_, KU1[0], m[0]); m[1] = fma2(d12_, KU1[1], m[1]); \
        m[2] = fma2(d12_, KU1[2], m[2]); m[3] = fma2(d12_, KU1[3], m[3]); \
        m[4] = fma2(d12_, KU1[4], m[4]); m[5] = fma2(d12_, KU1[5], m[5]); \
        m[6] = fma2(d12_, KU1[6], m[6]); m[7] = fma2(d12_, KU1[7], m[7]); \
        /* rotate */ \
        dm2 = d0_; dm1 = d1_; \
        g0 = g0n_; g1 = g1n_; g2 = g2n_; g3 = g3n_; g4 = g4n_; \
        hsc0 = sc0 * h0n_; csc0 = -C1 * sc0; \
        hsc1 = sc1 * h1n_; csc1 = -C1 * sc1; \
        vt0 = vt2; vt1 = vt3; vt2 = va_; vt3 = vb_; \
    }

    #pragma unroll 1
    for (int t = 3; t <= L_ - 5; t += 4) {
        PAIR(t,     kA0, kA1, kB0, kB1);
        PAIR(t + 2, kB0, kB1, kA0, kA1);
    }
    #undef PAIR
    #undef LOADK

    // ================= readout ==============================================
    // red0 = reduced k_{4095} . M^(4093); corrections d_{4093}, d_{4094}.
    {
        const float r = fmaf(dm1, g1, fmaf(dm2, g0, red0));
        if ((lane & 1) == 0) s_r[(is_e ? HALF_ : 0) + row] = r;
    }
    __syncthreads();

    // out = (r @ Wrp + brp) @ Wout + bout
    if (tid < H_) {
        float acc = brp[tid];
        #pragma unroll 16
        for (int k = 0; k < 2 * HALF_; ++k) acc = fmaf(s_r[k], Wrp[k * H_ + tid], acc);
        s_tmp[tid] = acc;
    }
    __syncthreads();
    if (tid < V_) {
        float acc = bout[tid];
        #pragma unroll 16
        for (int d = 0; d < H_; ++d) acc = fmaf(s_tmp[d], Wout[d * V_ + tid], acc);
        out[b * V_ + tid] = acc;
    }
}

// ---------------------------------------------------------------------------
extern "C" void kernel_launch(void* const* d_in, const int* in_sizes, int n_in,
                              void* d_out, int out_size)
{
    const int*   seq   = (const int*)d_in[0];
    const float* embed = (const float*)d_in[1];
    const float* W1    = (const float*)d_in[2];
    const float* b1    = (const float*)d_in[3];
    const float* W2    = (const float*)d_in[4];
    const float* b2    = (const float*)d_in[5];
    const float* gamma = (const float*)d_in[6];
    const float* beta  = (const float*)d_in[7];
    const float* Ws    = (const float*)d_in[8];
    const float* bs    = (const float*)d_in[9];
    const float* We    = (const float*)d_in[10];
    const float* be    = (const float*)d_in[11];
    const float* Wrp   = (const float*)d_in[12];
    const float* brp   = (const float*)d_in[13];
    const float* Wout  = (const float*)d_in[14];
    const float* bout  = (const float*)d_in[15];
    float* out = (float*)d_out;

    static int smem_set = 0;
    const int smem_bytes = (16384 + L_PAD + 128) * 4 + 256;
    if (!smem_set) {
        cudaFuncSetAttribute(scan_kernel,
                             cudaFuncAttributeMaxDynamicSharedMemorySize, smem_bytes);
        smem_set = 1;
    }

    build_tables<<<V_, 128>>>(embed, W1, b1, W2, b2, gamma, beta, Ws, bs, We, be);
    scan_kernel<<<B_, 128, smem_bytes>>>(seq, Wrp, brp, Wout, bout, out);
}

// round 10
// speedup vs baseline: 1.0018x; 1.0018x over previous
#include <cuda_runtime.h>

#define B_ 128
#define L_ 4096
#define H_ 64
#define V_ 64
#define HALF_ 32
#define C1 0.05f
#define LN_EPS 1e-5f
#define L_PAD (L_ + 8)

typedef unsigned long long ull;

// Token-indexed tables (V=64 tokens): g_hs/g_he are pre-scaled by (1-ALPHA)=C1.
__device__ float g_hs[V_ * HALF_];
__device__ float g_he[V_ * HALF_];
__device__ float g_ks[V_ * HALF_];
__device__ float g_ke[V_ * HALF_];

// ---------------- packed f32x2 helpers ----------------
__device__ __forceinline__ ull fma2(ull a, ull b, ull c) {
    ull d; asm("fma.rn.f32x2 %0,%1,%2,%3;" : "=l"(d) : "l"(a), "l"(b), "l"(c)); return d;
}
__device__ __forceinline__ ull mul2(ull a, ull b) {
    ull d; asm("mul.rn.f32x2 %0,%1,%2;" : "=l"(d) : "l"(a), "l"(b)); return d;
}
__device__ __forceinline__ ull add2(ull a, ull b) {
    ull d; asm("add.rn.f32x2 %0,%1,%2;" : "=l"(d) : "l"(a), "l"(b)); return d;
}
__device__ __forceinline__ ull pack2(float x) {
    ull d; asm("mov.b64 %0,{%1,%1};" : "=l"(d) : "f"(x)); return d;
}
__device__ __forceinline__ float2 unpack2(ull v) {
    float2 r; asm("mov.b64 {%0,%1},%2;" : "=f"(r.x), "=f"(r.y) : "l"(v)); return r;
}
__device__ __forceinline__ float reduce2(ull a0, ull a1) {
    ull s = add2(a0, a1);
    float2 f = unpack2(s);
    float h = f.x + f.y;
    return h + __shfl_xor_sync(0xffffffffu, h, 1);
}

// ---------------------------------------------------------------------------
// Kernel 1: per-token precompute. grid=64 (token), block=128.
// ---------------------------------------------------------------------------
__global__ void build_tables(const float* __restrict__ embed,
                             const float* __restrict__ W1, const float* __restrict__ b1,
                             const float* __restrict__ W2, const float* __restrict__ b2,
                             const float* __restrict__ gamma, const float* __restrict__ beta,
                             const float* __restrict__ Ws, const float* __restrict__ bs,
                             const float* __restrict__ We, const float* __restrict__ be)
{
    __shared__ float s_e[H_];
    __shared__ float s_a[2 * H_];
    __shared__ float s_x[H_];
    __shared__ float s_h[H_];
    __shared__ float s_mu, s_rstd;

    int tok = blockIdx.x;
    int tid = threadIdx.x;

    if (tid < H_) s_e[tid] = embed[tok * H_ + tid];
    __syncthreads();

    {
        float acc = b1[tid];
        #pragma unroll 32
        for (int h = 0; h < H_; ++h) acc = fmaf(s_e[h], __ldg(W1 + h * 2 * H_ + tid), acc);
        s_a[tid] = fmaxf(acc, 0.0f);
    }
    __syncthreads();

    if (tid < H_) {
        float acc = b2[tid];
        #pragma unroll 32
        for (int k = 0; k < 2 * H_; ++k) acc = fmaf(s_a[k], __ldg(W2 + k * H_ + tid), acc);
        s_x[tid] = s_e[tid] + acc;
    }
    __syncthreads();

    if (tid == 0) {
        float mu = 0.f;
        for (int i = 0; i < H_; ++i) mu += s_x[i];
        mu *= (1.0f / H_);
        float var = 0.f;
        for (int i = 0; i < H_; ++i) { float d = s_x[i] - mu; var = fmaf(d, d, var); }
        var *= (1.0f / H_);
        s_mu = mu;
        s_rstd = rsqrtf(var + LN_EPS);
    }
    __syncthreads();

    if (tid < H_) s_h[tid] = (s_x[tid] - s_mu) * s_rstd * gamma[tid] + beta[tid];
    __syncthreads();

    int wid = tid >> 5, lane = tid & 31;
    if (wid == 0) {
        float acc = bs[lane];
        #pragma unroll 32
        for (int j = 0; j < H_; ++j) acc = fmaf(s_h[j], __ldg(Ws + j * HALF_ + lane), acc);
        float ss = acc * acc;
        #pragma unroll
        for (int m = 16; m > 0; m >>= 1) ss += __shfl_xor_sync(0xffffffffu, ss, m);
        float n = fmaxf(sqrtf(ss), 1e-12f);
        g_hs[tok * HALF_ + lane] = C1 * acc;
        g_ks[tok * HALF_ + lane] = acc / n;
    } else if (wid == 1) {
        float acc = be[lane];
        #pragma unroll 32
        for (int j = 0; j < H_; ++j) acc = fmaf(s_h[j], __ldg(We + j * HALF_ + lane), acc);
        float ss = acc * acc;
        #pragma unroll
        for (int m = 16; m > 0; m >>= 1) ss += __shfl_xor_sync(0xffffffffu, ss, m);
        float n = fmaxf(sqrtf(ss), 1e-12f);
        g_he[tok * HALF_ + lane] = C1 * acc;
        g_ke[tok * HALF_ + lane] = acc / n;
    }
}

// ---------------------------------------------------------------------------
// Kernel 2: delta-rule scan, RANK-2 steps (token pair per iteration).
// grid = B (one batch per CTA/SM), block = 128 (4 warps -> 4 SMSPs).
// Warps 0,1: M_s; warps 2,3: M_e. Lane owns half a row (16 cols = 8 f32x2).
// Per iter (pair t,t+1):
//   - dots for pair (t+2,t+3) issued on PRE-update m = M^(t); reduced same
//     iter (shfl crosses iter boundary as loop-carried red0/red1)
//   - consumed next iter with 5 Gram corrections (d_{t-2}, d_{t-1}, d_t terms)
//   - serial chain: 4 FFMAs (d_{t-1} -> ps_t -> d_t -> ps_{t+1} -> d_{t+1})
// ---------------------------------------------------------------------------
__global__ __launch_bounds__(128, 1)
void scan_kernel(const int* __restrict__ seq,
                 const float* __restrict__ Wrp, const float* __restrict__ brp,
                 const float* __restrict__ Wout, const float* __restrict__ bout,
                 float* __restrict__ out)
{
    extern __shared__ float sm[];
    float* s_ks = sm;                          // 2048
    float* s_ke = sm + 2048;                   // 2048
    float* s_hs = sm + 4096;                   // 2048
    float* s_he = sm + 6144;                   // 2048
    float* s_Gs = sm + 8192;                   // 4096
    float* s_Ge = sm + 12288;                  // 4096
    int*   s_seq = (int*)(sm + 16384);         // L_+8 ints
    float* s_r   = sm + 16384 + L_PAD;         // 64
    float* s_tmp = s_r + 64;                   // 64

    const int b = blockIdx.x;
    const int tid = threadIdx.x;
    const int w = tid >> 5;
    const int lane = tid & 31;

    // stage sequence + tables
    {
        const int* seqb = seq + b * L_;
        for (int k = tid; k < L_; k += 128) s_seq[k] = seqb[k];
        if (tid < 8) s_seq[L_ + tid] = 0;
    }
    for (int k = tid; k < V_ * HALF_; k += 128) {
        s_ks[k] = g_ks[k];
        s_ke[k] = g_ke[k];
        s_hs[k] = g_hs[k];
        s_he[k] = g_he[k];
    }
    __syncthreads();

    // Gram tables computed in-CTA from staged keys (symmetric)
    for (int idx = tid; idx < V_ * V_; idx += 128) {
        const int a = idx >> 6, c = idx & 63;
        float ss = 0.f, se = 0.f;
        #pragma unroll
        for (int j = 0; j < HALF_; ++j) {
            ss = fmaf(s_ks[a * HALF_ + j], s_ks[c * HALF_ + j], ss);
            se = fmaf(s_ke[a * HALF_ + j], s_ke[c * HALF_ + j], se);
        }
        s_Gs[idx] = ss;
        s_Ge[idx] = se;
    }
    __syncthreads();

    const bool is_e = (w >= 2);
    const int row = ((w & 1) << 4) | (lane >> 1);
    const int col0 = (lane & 1) << 4;
    const float* kT = is_e ? s_ke : s_ks;
    const float* hT = is_e ? s_he : s_hs;
    const float* gT = is_e ? s_Ge : s_Gs;
    const float invL = 1.0f / (float)L_;

    ull m[8], kA0[8], kA1[8], kB0[8], kB1[8], kt[8];

    #define LOADK(DST, TOK) { \
        const ulonglong2* p_ = (const ulonglong2*)(kT + ((TOK) << 5) + col0); \
        ulonglong2 x_ = p_[0], y_ = p_[1]; \
        DST[0] = x_.x; DST[1] = x_.y; DST[2] = y_.x; DST[3] = y_.y; \
        const ulonglong2* q_ = (const ulonglong2*)(kT + ((TOK) << 5) + col0 + 8); \
        ulonglong2 z_ = q_[0], u_ = q_[1]; \
        DST[4] = z_.x; DST[5] = z_.y; DST[6] = u_.x; DST[7] = u_.y; }

    // ================= prologue: steps 0,1,2 =================
    const int v0 = s_seq[0], v1 = s_seq[1], v2 = s_seq[2];
    int vt0 = s_seq[3], vt1 = s_seq[4], vt2 = s_seq[5], vt3 = s_seq[6];

    const float sc_0 = is_e ? invL : 1.0f;
    const float sc_1 = is_e ? 2.0f * invL : 1.0f;
    const float sc_2 = is_e ? 3.0f * invL : 1.0f;

    // step 0 (ps = 0)
    const float d0p = sc_0 * hT[(v0 << 5) + row];
    LOADK(kt, v0);
    {
        const ull d2_ = pack2(d0p);
        #pragma unroll
        for (int j = 0; j < 8; ++j) m[j] = mul2(d2_, kt[j]);     // M^(1)
    }

    // dots of k_3, k_4 on M^(1) (pre-update relative to pair (1,2))
    LOADK(kA0, vt0);
    LOADK(kA1, vt1);
    float red0, red1;
    {
        ull a0 = mul2(m[0], kA0[0]), a1 = mul2(m[1], kA0[1]);
        a0 = fma2(m[2], kA0[2], a0); a1 = fma2(m[3], kA0[3], a1);
        a0 = fma2(m[4], kA0[4], a0); a1 = fma2(m[5], kA0[5], a1);
        a0 = fma2(m[6], kA0[6], a0); a1 = fma2(m[7], kA0[7], a1);
        ull b0 = mul2(m[0], kA1[0]), b1 = mul2(m[1], kA1[1]);
        b0 = fma2(m[2], kA1[2], b0); b1 = fma2(m[3], kA1[3], b1);
        b0 = fma2(m[4], kA1[4], b0); b1 = fma2(m[5], kA1[5], b1);
        b0 = fma2(m[6], kA1[6], b0); b1 = fma2(m[7], kA1[7], b1);
        red0 = reduce2(a0, a1);
        red1 = reduce2(b0, b1);
    }

    // steps 1,2 (exact ps via Gram)
    const float g01 = gT[(v0 << 6) + v1];
    const float g02 = gT[(v0 << 6) + v2];
    const float g12 = gT[(v1 << 6) + v2];
    const float ps1p = d0p * g01;
    const float d1p = fmaf(-C1 * sc_1, ps1p, sc_1 * hT[(v1 << 5) + row]);
    const float ps2p = fmaf(d1p, g12, d0p * g02);
    const float d2p = fmaf(-C1 * sc_2, ps2p, sc_2 * hT[(v2 << 5) + row]);
    LOADK(kt, v1);
    {
        const ull d2_ = pack2(d1p);
        #pragma unroll
        for (int j = 0; j < 8; ++j) m[j] = fma2(d2_, kt[j], m[j]);
    }
    LOADK(kt, v2);
    {
        const ull d2_ = pack2(d2p);
        #pragma unroll
        for (int j = 0; j < 8; ++j) m[j] = fma2(d2_, kt[j], m[j]);   // M^(3)
    }

    float dm2 = d1p, dm1 = d2p;

    // scalars for pair (3,4)
    float g0 = gT[(vt0 << 6) + v1];   // G(v1, v3)
    float g1 = gT[(vt0 << 6) + v2];   // G(v2, v3)
    float g2 = gT[(vt1 << 6) + v1];   // G(v1, v4)
    float g3 = gT[(vt1 << 6) + v2];   // G(v2, v4)
    float g4 = gT[(vt1 << 6) + vt0];  // G(v3, v4)
    float sc0 = is_e ? 4.0f * invL : 1.0f;
    float sc1 = is_e ? 5.0f * invL : 1.0f;
    const float sc2step = is_e ? 2.0f * invL : 0.0f;
    float hsc0 = sc0 * hT[(vt0 << 5) + row], csc0 = -C1 * sc0;
    float hsc1 = sc1 * hT[(vt1 << 5) + row], csc1 = -C1 * sc1;

    // ================= main loop: pairs (t, t+1), t = 3,5,...,4093 ==========
    #define PAIR(T, KU0, KU1, KL0, KL1) { \
        const int va_ = s_seq[(T) + 4]; \
        const int vb_ = s_seq[(T) + 5]; \
        LOADK(KL0, vt2); \
        LOADK(KL1, vt3); \
        /* serial chain (4 FFMAs from dm1) */ \
        const float ps0_ = fmaf(dm1, g1, fmaf(dm2, g0, red0)); \
        const float d0_  = fmaf(csc0, ps0_, hsc0); \
        const float ps1_ = fmaf(d0_, g4, fmaf(dm1, g3, fmaf(dm2, g2, red1))); \
        const float d1_  = fmaf(csc1, ps1_, hsc1); \
        /* dots of k_{T+2},k_{T+3} on PRE-update m = M^(T) */ \
        ull a0_ = mul2(m[0], KL0[0]), a1_ = mul2(m[1], KL0[1]); \
        a0_ = fma2(m[2], KL0[2], a0_); a1_ = fma2(m[3], KL0[3], a1_); \
        a0_ = fma2(m[4], KL0[4], a0_); a1_ = fma2(m[5], KL0[5], a1_); \
        a0_ = fma2(m[6], KL0[6], a0_); a1_ = fma2(m[7], KL0[7], a1_); \
        ull b0_ = mul2(m[0], KL1[0]), b1_ = mul2(m[1], KL1[1]); \
        b0_ = fma2(m[2], KL1[2], b0_); b1_ = fma2(m[3], KL1[3], b1_); \
        b0_ = fma2(m[4], KL1[4], b0_); b1_ = fma2(m[5], KL1[5], b1_); \
        b0_ = fma2(m[6], KL1[6], b0_); b1_ = fma2(m[7], KL1[7], b1_); \
        red0 = reduce2(a0_, a1_); \
        red1 = reduce2(b0_, b1_); \
        /* next-pair Gram / h / scale prefetch (all off-chain) */ \
        const int b2_ = vt2 << 6, b3_ = vt3 << 6; \
        const float g0n_ = gT[b2_ + vt0], g1n_ = gT[b2_ + vt1]; \
        const float g2n_ = gT[b3_ + vt0], g3n_ = gT[b3_ + vt1], g4n_ = gT[b3_ + vt2]; \
        const float h0n_ = hT[(vt2 << 5) + row], h1n_ = hT[(vt3 << 5) + row]; \
        sc0 += sc2step; sc1 += sc2step; \
        /* rank-2 update: m = M^(T+2) */ \
        const ull d02_ = pack2(d0_), d12_ = pack2(d1_); \
        m[0] = fma2(d02_, KU0[0], m[0]); m[1] = fma2(d02_, KU0[1], m[1]); \
        m[2] = fma2(d02_, KU0[2], m[2]); m[3] = fma2(d02_, KU0[3], m[3]); \
        m[4] = fma2(d02_, KU0[4], m[4]); m[5] = fma2(d02_, KU0[5], m[5]); \
        m[6] = fma2(d02_, KU0[6], m[6]); m[7] = fma2(d02_, KU0[7], m[7]); \
        m[0] = fma2(d12_, KU1[0], m[0]); m[1] = fma2(d12_, KU1[1], m[1]); \
        m[2] = fma2(d12_, KU1[2], m[2]); m[3] = fma2(d12_, KU1[3], m[3]); \
        m[4] = fma2(d12_, KU1[4], m[4]); m[5] = fma2(d12_, KU1[5], m[5]); \
        m[6] = fma2(d12_, KU1[6], m[6]); m[7] = fma2(d12_, KU1[7], m[7]); \
        /* rotate */ \
        dm2 = d0_; dm1 = d1_; \
        g0 = g0n_; g1 = g1n_; g2 = g2n_; g3 = g3n_; g4 = g4n_; \
        hsc0 = sc0 * h0n_; csc0 = -C1 * sc0; \
        hsc1 = sc1 * h1n_; csc1 = -C1 * sc1; \
        vt0 = vt2; vt1 = vt3; vt2 = va_; vt3 = vb_; \
    }

    #pragma unroll 1
    for (int t = 3; t <= L_ - 5; t += 4) {
        PAIR(t,     kA0, kA1, kB0, kB1);
        PAIR(t + 2, kB0, kB1, kA0, kA1);
    }
    #undef PAIR
    #undef LOADK

    // ================= readout ==============================================
    // red0 = reduced k_{4095} . M^(4093); corrections d_{4093}, d_{4094}.
    {
        const float r = fmaf(dm1, g1, fmaf(dm2, g0, red0));
        if ((lane & 1) == 0) s_r[(is_e ? HALF_ : 0) + row] = r;
    }
    __syncthreads();

    // out = (r @ Wrp + brp) @ Wout + bout
    if (tid < H_) {
        float acc = brp[tid];
        #pragma unroll 16
        for (int k = 0; k < 2 * HALF_; ++k) acc = fmaf(s_r[k], Wrp[k * H_ + tid], acc);
        s_tmp[tid] = acc;
    }
    __syncthreads();
    if (tid < V_) {
        float acc = bout[tid];
        #pragma unroll 16
        for (int d = 0; d < H_; ++d) acc = fmaf(s_tmp[d], Wout[d * V_ + tid], acc);
        out[b * V_ + tid] = acc;
    }
}

// ---------------------------------------------------------------------------
extern "C" void kernel_launch(void* const* d_in, const int* in_sizes, int n_in,
                              void* d_out, int out_size)
{
    const int*   seq   = (const int*)d_in[0];
    const float* embed = (const float*)d_in[1];
    const float* W1    = (const float*)d_in[2];
    const float* b1    = (const float*)d_in[3];
    const float* W2    = (const float*)d_in[4];
    const float* b2    = (const float*)d_in[5];
    const float* gamma = (const float*)d_in[6];
    const float* beta  = (const float*)d_in[7];
    const float* Ws    = (const float*)d_in[8];
    const float* bs    = (const float*)d_in[9];
    const float* We    = (const float*)d_in[10];
    const float* be    = (const float*)d_in[11];
    const float* Wrp   = (const float*)d_in[12];
    const float* brp   = (const float*)d_in[13];
    const float* Wout  = (const float*)d_in[14];
    const float* bout  = (const float*)d_in[15];
    float* out = (float*)d_out;

    static int smem_set = 0;
    const int smem_bytes = (16384 + L_PAD + 128) * 4 + 256;
    if (!smem_set) {
        cudaFuncSetAttribute(scan_kernel,
                             cudaFuncAttributeMaxDynamicSharedMemorySize, smem_bytes);
        smem_set = 1;
    }

    build_tables<<<V_, 128>>>(embed, W1, b1, W2, b2, gamma, beta, Ws, bs, We, be);
    scan_kernel<<<B_, 128, smem_bytes>>>(seq, Wrp, brp, Wout, bout, out);
}